// round 10
// baseline (speedup 1.0000x reference)
#include <cuda_runtime.h>
#include <cuda_bf16.h>
#include <cstdint>

// Problem constants (fixed for this dataset)
#define NN 100000
#define EE 1600000
#define C_IN 128
#define C_OUT 64

// ---------------- device scratch (no allocations allowed) ----------------
__device__ float g_tx[4][(size_t)NN * C_OUT];  // Tx0(=h), Tx1, Tx2, Tx3
__device__ int   g_off[NN + 1];
__device__ int   g_cnt[NN];
__device__ int   g_cur[NN];
__device__ int2  g_edge[EE];                   // packed (src, val-bits)
__device__ int   g_part[128];
__device__ int   g_flag64;

// ---------------- helpers ----------------
__device__ __forceinline__ int load_idx(const void* p, int e) {
    if (g_flag64) return (int)((const long long*)p)[e];
    return ((const int*)p)[e];
}

// ---------------- init: zero counters + detect int32 vs int64 indices ----
__global__ void init_kernel(const void* esrc, int n) {
    int i = blockIdx.x * blockDim.x + threadIdx.x;
    for (; i < n; i += gridDim.x * blockDim.x) { g_cnt[i] = 0; g_cur[i] = 0; }
    if (blockIdx.x == 0 && threadIdx.x == 0) {
        const int* w = (const int*)esrc;
        int flag = 1;
        for (int k = 0; k < 128; k++) {
            if (w[2 * k + 1] != 0) { flag = 0; break; }
        }
        g_flag64 = flag;
    }
}

// ---------------- CSR build ----------------
__global__ void hist_kernel(const void* edst, int E) {
    int e = blockIdx.x * blockDim.x + threadIdx.x;
    if (e >= E) return;
    int d = load_idx(edst, e);
    atomicAdd(&g_cnt[d], 1);
}

__global__ void scan1_kernel(int n) {
    __shared__ int sh[1024];
    int t = threadIdx.x;
    int i = blockIdx.x * 1024 + t;
    int v = (i < n) ? g_cnt[i] : 0;
    sh[t] = v;
    __syncthreads();
    for (int o = 1; o < 1024; o <<= 1) {
        int x = 0;
        if (t >= o) x = sh[t - o];
        __syncthreads();
        sh[t] += x;
        __syncthreads();
    }
    if (i < n) g_off[i] = sh[t] - v;       // exclusive within chunk
    if (t == 1023) g_part[blockIdx.x] = sh[1023];
}

__global__ void scan2_kernel(int nb, int n, int E) {
    __shared__ int sh[128];
    int t = threadIdx.x;
    int v = (t < nb) ? g_part[t] : 0;
    sh[t] = v;
    __syncthreads();
    for (int o = 1; o < 128; o <<= 1) {
        int x = 0;
        if (t >= o) x = sh[t - o];
        __syncthreads();
        sh[t] += x;
        __syncthreads();
    }
    if (t < nb) g_part[t] = sh[t] - v;     // exclusive chunk offsets
    if (t == 0) g_off[n] = E;
}

__global__ void scan3_kernel(int n) {
    int i = blockIdx.x * blockDim.x + threadIdx.x;
    if (i < n) g_off[i] += g_part[i >> 10];
}

__global__ void scatter_kernel(const void* esrc, const void* edst, const float* evals, int E) {
    int e = blockIdx.x * blockDim.x + threadIdx.x;
    if (e >= E) return;
    int s = load_idx(esrc, e);
    int d = load_idx(edst, e);
    float v = evals[e];
    int p = g_off[d] + atomicAdd(&g_cur[d], 1);
    int2 rec; rec.x = s; rec.y = __float_as_int(v);
    g_edge[p] = rec;
}

// ---------------- input GEMM: h = relu(x @ W_in + b_in) ----------------
// 256 threads = 64 channels x 4 nodes; warp = 8ch x 4nodes -> weight LDS
// addresses depend only on c => 8 distinct/warp => broadcast-dedup 4x.
// 8-node tile: 2 accumulation passes per tile, halved barrier count.
__global__ void gemm_in_kernel(const float* __restrict__ x,
                               const float* __restrict__ Win,
                               const float* __restrict__ bin, int n) {
    __shared__ float sW[64 * 132];     // transposed, stride 132 (4c mod 32 pattern)
    __shared__ float sx[8 * 132];      // 8 nodes, stride 132
    int tid = threadIdx.x;
    for (int idx = tid; idx < C_IN * C_OUT; idx += 256) {
        int i = idx >> 6, cc = idx & 63;
        sW[cc * 132 + i] = Win[idx];
    }
    int c = tid >> 2;       // 0..63
    int j = tid & 3;        // node within quad
    float bc = __ldg(&bin[c]);
    __syncthreads();

    const float4* wrow = (const float4*)&sW[c * 132];   // 32 float4s used

    for (int base = blockIdx.x * 8; base < n; base += gridDim.x * 8) {
        for (int idx = tid; idx < 1024; idx += 256) {
            int jj = idx >> 7, i = idx & 127;
            int nid2 = base + jj;
            sx[jj * 132 + i] = (nid2 < n) ? x[(size_t)nid2 * 128 + i] : 0.f;
        }
        __syncthreads();
#pragma unroll
        for (int half = 0; half < 2; half++) {
            int jj = half * 4 + j;
            float acc = bc;
            const float4* xv = (const float4*)&sx[jj * 132];
#pragma unroll
            for (int i = 0; i < 32; i++) {
                float4 a = wrow[i], b = xv[i];
                acc += a.x * b.x + a.y * b.y + a.z * b.z + a.w * b.w;
            }
            int nid = base + jj;
            if (nid < n) g_tx[0][(size_t)nid * 64 + c] = fmaxf(acc, 0.0f);
        }
        __syncthreads();
    }
}

// ---------------- SpMM (CSR by dst): Tx[ds] = L @ Tx[ss] ----------------
// 16 threads per dst node, each owns one float4 (4 channels). No atomics.
// Packed 8B edge records + 4-edge unroll to raise MLP (avg degree 16).
__global__ void spmm_csr_kernel(int ss, int ds, int n) {
    int idx = blockIdx.x * blockDim.x + threadIdx.x;
    int d = idx >> 4;
    int q = idx & 15;
    if (d >= n) return;
    int r0 = __ldg(&g_off[d]), r1 = __ldg(&g_off[d + 1]);
    float ax = 0.f, ay = 0.f, az = 0.f, aw = 0.f;
    float bx = 0.f, by = 0.f, bz = 0.f, bw = 0.f;
    const float4* __restrict__ src_base = (const float4*)g_tx[ss];
    const int2*  __restrict__ edges = g_edge;
    int e = r0;
    for (; e + 3 < r1; e += 4) {
        int2 r_0 = __ldg(&edges[e]);
        int2 r_1 = __ldg(&edges[e + 1]);
        int2 r_2 = __ldg(&edges[e + 2]);
        int2 r_3 = __ldg(&edges[e + 3]);
        float4 a0 = __ldg(&src_base[(size_t)r_0.x * 16 + q]);
        float4 a1 = __ldg(&src_base[(size_t)r_1.x * 16 + q]);
        float4 a2 = __ldg(&src_base[(size_t)r_2.x * 16 + q]);
        float4 a3 = __ldg(&src_base[(size_t)r_3.x * 16 + q]);
        float v0 = __int_as_float(r_0.y);
        float v1 = __int_as_float(r_1.y);
        float v2 = __int_as_float(r_2.y);
        float v3 = __int_as_float(r_3.y);
        ax += v0 * a0.x; ay += v0 * a0.y; az += v0 * a0.z; aw += v0 * a0.w;
        bx += v1 * a1.x; by += v1 * a1.y; bz += v1 * a1.z; bw += v1 * a1.w;
        ax += v2 * a2.x; ay += v2 * a2.y; az += v2 * a2.z; aw += v2 * a2.w;
        bx += v3 * a3.x; by += v3 * a3.y; bz += v3 * a3.z; bw += v3 * a3.w;
    }
    for (; e < r1; e++) {
        int2 r_0 = __ldg(&edges[e]);
        float v0 = __int_as_float(r_0.y);
        float4 a = __ldg(&src_base[(size_t)r_0.x * 16 + q]);
        ax += v0 * a.x; ay += v0 * a.y; az += v0 * a.z; aw += v0 * a.w;
    }
    float4 r; r.x = ax + bx; r.y = ay + by; r.z = az + bz; r.w = aw + bw;
    ((float4*)(g_tx[ds]))[(size_t)d * 16 + q] = r;
}

// ---------------- fused epilogue ----------------
// Thread map: c = tid>>2 (output channel), j = tid&3 (node). Warp = 8ch x
// 4 nodes -> weight smem loads dedup 4x via broadcast rule.
#define WS 68      // weight row stride (floats): 4c mod 32 -> conflict-free
#define AS 72      // activation row stride:      8j mod 32 -> conflict-free
__global__ void epilogue_kernel(const float* __restrict__ thetas,
                                const float* __restrict__ Wb, const float* __restrict__ bWb,
                                const float* __restrict__ Wx, const float* __restrict__ bWx,
                                const float* __restrict__ vc,
                                const float* __restrict__ W1, const float* __restrict__ b1,
                                const float* __restrict__ W2, const float* __restrict__ b2,
                                const float* __restrict__ W3, const float* __restrict__ b3,
                                float* __restrict__ out, int n) {
    extern __shared__ float sm[];
    float* sWb  = sm;                 // 64*WS
    float* sWx  = sWb + 64 * WS;      // 64*WS
    float* sW1  = sWx + 64 * WS;      // 64*WS
    float* sW2  = sW1 + 64 * WS;      // 32*WS
    float* sW3  = sW2 + 32 * WS;      // 64
    float* svc  = sW3 + 64;           // 64
    float* sbWb = svc + 64;           // 64
    float* sbWx = sbWb + 64;          // 64
    float* sb1  = sbWx + 64;          // 64
    float* sb2  = sb1 + 64;           // 32
    float* sb3  = sb2 + 32;           // 2 (+2 pad)
    float* sp0  = sb3 + 4;            // 4*AS
    float* sp1  = sp0 + 4 * AS;
    float* shh  = sp1 + 4 * AS;
    float* sres = shh + 4 * AS;
    float* sy1  = sres + 4 * AS;
    float* sy2  = sy1 + 4 * AS;       // 4*36
    float* sred0= sy2 + 4 * 36;       // 32 = 8 warps x 4 nodes
    float* sred1= sred0 + 32;         // 32

    int tid = threadIdx.x;
    for (int idx = tid; idx < 4096; idx += 256) {
        int i = idx >> 6, cc = idx & 63;
        sWb[cc * WS + i] = Wb[idx];
        sWx[cc * WS + i] = Wx[idx];
        sW1[cc * WS + i] = W1[idx];
    }
    for (int idx = tid; idx < 2048; idx += 256) {
        int i = idx >> 5, cc = idx & 31;
        sW2[cc * WS + i] = W2[idx];
    }
    if (tid < 64) {
        sW3[tid]  = W3[tid];
        svc[tid]  = vc[tid];
        sbWb[tid] = bWb[tid];
        sbWx[tid] = bWx[tid];
        sb1[tid]  = b1[tid];
    }
    if (tid < 32) sb2[tid] = b2[tid];
    if (tid < 2)  sb3[tid] = b3[tid];

    // fold thetas with Bernstein coefficients
    float th0 = __ldg(&thetas[0]), th1 = __ldg(&thetas[1]), th2 = __ldg(&thetas[2]), th3 = __ldg(&thetas[3]);
    float tg0 = __ldg(&thetas[4]), tg1 = __ldg(&thetas[5]), tg2 = __ldg(&thetas[6]), tg3 = __ldg(&thetas[7]);
    float c00 = th0;
    float c01 = -3.f * th0 + 3.f * th1;
    float c02 =  3.f * th0 - 6.f * th1 + 3.f * th2;
    float c03 = -1.f * th0 + 3.f * th1 - 3.f * th2 + th3;
    float c10 = tg0;
    float c11 = -3.f * tg0 + 3.f * tg1;
    float c12 =  3.f * tg0 - 6.f * tg1 + 3.f * tg2;
    float c13 = -1.f * tg0 + 3.f * tg1 - 3.f * tg2 + tg3;
    __syncthreads();

    int c = tid >> 2;         // 0..63 output channel
    int j = tid & 3;          // node within quad
    int lane = tid & 31;
    int warp = tid >> 5;

    const float4* wbr = (const float4*)&sWb[c * WS];
    const float4* wxr = (const float4*)&sWx[c * WS];
    const float4* w1r = (const float4*)&sW1[c * WS];
    const float4* w2r = (const float4*)&sW2[(c & 31) * WS];

    for (int base = blockIdx.x * 4; base < n; base += gridDim.x * 4) {
        int nid = base + j;
        bool ok = nid < n;
        float t0 = 0.f, t1v = 0.f, t2v = 0.f, t3v = 0.f;
        if (ok) {
            size_t o = (size_t)nid * 64 + c;
            t0  = g_tx[0][o];
            t1v = g_tx[1][o];
            t2v = g_tx[2][o];
            t3v = g_tx[3][o];
        }
        float p0 = c00 * t0 + c01 * t1v + c02 * t2v + c03 * t3v;
        float p1 = c10 * t0 + c11 * t1v + c12 * t2v + c13 * t3v;
        sp0[j * AS + c] = p0;
        sp1[j * AS + c] = p1;
        shh[j * AS + c] = t0;
        __syncthreads();

        // pp0 = poly0@Wb + bWb ; pp1 = poly1@Wb + bWb ; xp = h@Wx + bWx
        float pp0 = sbWb[c], pp1 = sbWb[c], xp = sbWx[c];
        const float4* v0 = (const float4*)&sp0[j * AS];
        const float4* v1 = (const float4*)&sp1[j * AS];
        const float4* vh = (const float4*)&shh[j * AS];
#pragma unroll
        for (int i = 0; i < 16; i++) {
            float4 a = wbr[i], b = wxr[i], u = v0[i], w = v1[i], hh = vh[i];
            pp0 += a.x * u.x + a.y * u.y + a.z * u.z + a.w * u.w;
            pp1 += a.x * w.x + a.y * w.y + a.z * w.z + a.w * w.w;
            xp  += b.x * hh.x + b.y * hh.y + b.z * hh.z + b.w * hh.w;
        }
        float vcc = svc[c];
        float term0 = tanhf(pp0 + xp) * vcc;
        float term1 = tanhf(pp1 + xp) * vcc;
        // reduce over the 8 channels of this warp (lanes with same j are 4 apart)
#pragma unroll
        for (int o = 4; o < 32; o <<= 1) {
            term0 += __shfl_xor_sync(0xffffffffu, term0, o);
            term1 += __shfl_xor_sync(0xffffffffu, term1, o);
        }
        if (lane < 4) {
            sred0[warp * 4 + lane] = term0;
            sred1[warp * 4 + lane] = term1;
        }
        __syncthreads();
        float s0 = 0.f, s1 = 0.f;
#pragma unroll
        for (int w8 = 0; w8 < 8; w8++) {
            s0 += sred0[w8 * 4 + j];
            s1 += sred1[w8 * 4 + j];
        }
        float att0 = 1.f / (1.f + expf(s1 - s0));
        float att1 = 1.f - att0;
        float res = att0 * p0 + att1 * p1;
        sres[j * AS + c] = res;
        __syncthreads();

        // y1 = relu(res@W1 + b1)
        float y = sb1[c];
        const float4* vr = (const float4*)&sres[j * AS];
#pragma unroll
        for (int i = 0; i < 16; i++) {
            float4 a = w1r[i], r4 = vr[i];
            y += a.x * r4.x + a.y * r4.y + a.z * r4.z + a.w * r4.w;
        }
        sy1[j * AS + c] = fmaxf(y, 0.f);
        __syncthreads();

        // y2 = relu(y1@W2 + b2)  (32 outputs; threads tid<128)
        if (c < 32) {
            float z = sb2[c];
            const float4* vy = (const float4*)&sy1[j * AS];
#pragma unroll
            for (int i = 0; i < 16; i++) {
                float4 a = w2r[i], r4 = vy[i];
                z += a.x * r4.x + a.y * r4.y + a.z * r4.z + a.w * r4.w;
            }
            sy2[j * 36 + c] = fmaxf(z, 0.f);
        }
        __syncthreads();

        // y_hat = y2@W3 + b3 (2 outputs x 4 nodes = threads tid<8)
        if (ok && c < 2) {
            float o = sb3[c];
#pragma unroll
            for (int i = 0; i < 32; i++) o += sy2[j * 36 + i] * sW3[i * 2 + c];
            out[(size_t)nid * 2 + c] = o;
        }
        __syncthreads();
    }
}

// ---------------- host launcher ----------------
extern "C" void kernel_launch(void* const* d_in, const int* in_sizes, int n_in,
                              void* d_out, int out_size) {
    const float* x     = (const float*)d_in[0];
    const void*  esrc  = d_in[1];
    const void*  edst  = d_in[2];
    const float* evals = (const float*)d_in[3];
    const float* Win   = (const float*)d_in[4];
    const float* bin   = (const float*)d_in[5];
    const float* thetas= (const float*)d_in[6];
    const float* Wb    = (const float*)d_in[7];
    const float* bWb   = (const float*)d_in[8];
    const float* Wx    = (const float*)d_in[9];
    const float* bWx   = (const float*)d_in[10];
    const float* vc    = (const float*)d_in[11];
    const float* W1    = (const float*)d_in[12];
    const float* b1    = (const float*)d_in[13];
    const float* W2    = (const float*)d_in[14];
    const float* b2    = (const float*)d_in[15];
    const float* W3    = (const float*)d_in[16];
    const float* b3    = (const float*)d_in[17];
    float* out = (float*)d_out;

    int n = in_sizes[0] / C_IN;     // 100000
    int E = in_sizes[3];            // 1600000

    // 1) init counters + index-width detection
    init_kernel<<<256, 256>>>(esrc, n);

    // 2) CSR build (reused for all 3 hops)
    int eb = (E + 255) / 256;
    hist_kernel<<<eb, 256>>>(edst, E);
    int nb = (n + 1023) / 1024;     // 98
    scan1_kernel<<<nb, 1024>>>(n);
    scan2_kernel<<<1, 128>>>(nb, n, E);
    scan3_kernel<<<(n + 255) / 256, 256>>>(n);
    scatter_kernel<<<eb, 256>>>(esrc, edst, evals, E);

    // 3) input transform: h = relu(x@W_in + b_in) -> Tx0
    gemm_in_kernel<<<888, 256>>>(x, Win, bin, n);

    // 4) 3 chained SpMMs (no atomics, gathers hit L2)
    int sb = (n * 16 + 255) / 256;
    spmm_csr_kernel<<<sb, 256>>>(0, 1, n);
    spmm_csr_kernel<<<sb, 256>>>(1, 2, n);
    spmm_csr_kernel<<<sb, 256>>>(2, 3, n);

    // 5) fused polynomial + attention + MLP head
    size_t smem = (size_t)(3 * 64 * WS + 32 * WS + 64 * 5 + 32 + 4 + 5 * 4 * AS + 4 * 36 + 64 + 16) * sizeof(float);
    cudaFuncSetAttribute(epilogue_kernel, cudaFuncAttributeMaxDynamicSharedMemorySize, (int)smem);
    epilogue_kernel<<<444, 256, smem>>>(thetas, Wb, bWb, Wx, bWx, vc,
                                        W1, b1, W2, b2, W3, b3, out, n);
    (void)n_in; (void)out_size;
}

// round 14
// speedup vs baseline: 1.0930x; 1.0930x over previous
#include <cuda_runtime.h>
#include <cuda_bf16.h>
#include <cstdint>

// Problem constants (fixed for this dataset)
#define NN 100000
#define EE 1600000
#define C_IN 128
#define C_OUT 64

// ---------------- device scratch (no allocations allowed) ----------------
__device__ float g_tx[4][(size_t)NN * C_OUT];  // Tx0(=h), Tx1, Tx2, Tx3
__device__ int   g_off[NN];       // scan: exclusive prefix; scatter mutates to row-end
__device__ int   g_cnt[NN];       // zero at entry (loader zero-init / scan self-reset)
__device__ int2  g_edge[EE];      // packed (src, val-bits)
__device__ volatile unsigned int g_tpack[128];  // lookback: (value<<2)|status
__device__ int   g_flag64;

// ---------------- helpers ----------------
__device__ __forceinline__ int load_idx(const void* p, int e) {
    if (g_flag64) return (int)((const long long*)p)[e];
    return ((const int*)p)[e];
}

// ---------------- detect int32/int64 + reset lookback flags ----------------
__global__ void detect_kernel(const void* esrc) {
    int t = threadIdx.x;
    if (t < 128) g_tpack[t] = 0u;
    if (t == 0) {
        const int* w = (const int*)esrc;
        int flag = 1;
        for (int k = 0; k < 128; k++) {
            if (w[2 * k + 1] != 0) { flag = 0; break; }
        }
        g_flag64 = flag;
    }
}

// ---------------- histogram of dst ----------------
__global__ void hist_kernel(const void* edst, int E) {
    int e = blockIdx.x * blockDim.x + threadIdx.x;
    if (e >= E) return;
    int d = load_idx(edst, e);
    atomicAdd(&g_cnt[d], 1);
}

// ---------------- single-pass decoupled-lookback exclusive scan ----------------
// 98 blocks x 1024 threads (all resident: 98 <= 148 SMs -> no deadlock).
// Also resets g_cnt to zero for the next graph replay.
__global__ void scan_kernel(int n) {
    __shared__ int sh[1024];
    __shared__ int s_prefix;
    int b = blockIdx.x, t = threadIdx.x;
    int i = b * 1024 + t;
    int v = (i < n) ? g_cnt[i] : 0;
    if (i < n) g_cnt[i] = 0;
    sh[t] = v;
    __syncthreads();
    for (int o = 1; o < 1024; o <<= 1) {
        int x = (t >= o) ? sh[t - o] : 0;
        __syncthreads();
        sh[t] += x;
        __syncthreads();
    }
    int incl = sh[t];
    int total = sh[1023];
    if (t == 0) {
        if (b == 0) {
            __threadfence();
            g_tpack[0] = ((unsigned)total << 2) | 2u;
            s_prefix = 0;
        } else {
            __threadfence();
            g_tpack[b] = ((unsigned)total << 2) | 1u;   // publish aggregate
            int sum = 0;
            int p = b - 1;
            while (p >= 0) {
                unsigned pk;
                do { pk = g_tpack[p]; } while ((pk & 3u) == 0u);
                sum += (int)(pk >> 2);
                if ((pk & 3u) == 2u) break;
                p--;
            }
            __threadfence();
            g_tpack[b] = ((unsigned)(sum + total) << 2) | 2u;  // publish prefix
            s_prefix = sum;
        }
    }
    __syncthreads();
    if (i < n) g_off[i] = s_prefix + incl - v;   // exclusive prefix
}

// ---------------- scatter: bump g_off[d] as the cursor ----------------
// After this kernel, g_off[d] == end of row d; row d = [g_off[d-1], g_off[d]).
__global__ void scatter_kernel(const void* esrc, const void* edst, const float* evals, int E) {
    int e = blockIdx.x * blockDim.x + threadIdx.x;
    if (e >= E) return;
    int s = load_idx(esrc, e);
    int d = load_idx(edst, e);
    float v = evals[e];
    int p = atomicAdd(&g_off[d], 1);
    int2 rec; rec.x = s; rec.y = __float_as_int(v);
    g_edge[p] = rec;
}

// ---------------- input GEMM: h = relu(x @ W_in + b_in) ----------------
// R3 layout (measured best): block = 4 nodes x 64 channels, warp = 32
// channels of one node; padded transposed weights in smem.
__global__ void gemm_in_kernel(const float* __restrict__ x,
                               const float* __restrict__ Win,
                               const float* __restrict__ bin, int n) {
    __shared__ float sW[64 * 132];     // transposed, stride 132 -> conflict free
    __shared__ float sx[4 * 128];
    int tid = threadIdx.x;
    for (int idx = tid; idx < C_IN * C_OUT; idx += 256) {
        int i = idx >> 6, c = idx & 63;
        sW[c * 132 + i] = Win[idx];
    }
    int node = tid >> 6;
    int c = tid & 63;
    float bc = __ldg(&bin[c]);
    __syncthreads();

    for (int base = blockIdx.x * 4; base < n; base += gridDim.x * 4) {
        int nid = base + node;
        bool ok = nid < n;
        if (ok) {
            sx[node * 128 + c]      = x[(size_t)nid * 128 + c];
            sx[node * 128 + 64 + c] = x[(size_t)nid * 128 + 64 + c];
        }
        __syncthreads();
        float acc = bc;
        const float4* w  = (const float4*)&sW[c * 132];
        const float4* xv = (const float4*)&sx[node * 128];
#pragma unroll
        for (int i = 0; i < 32; i++) {
            float4 a = w[i], b = xv[i];
            acc += a.x * b.x + a.y * b.y + a.z * b.z + a.w * b.w;
        }
        if (ok) g_tx[0][(size_t)nid * 64 + c] = fmaxf(acc, 0.0f);
        __syncthreads();
    }
}

// ---------------- SpMM (CSR by dst): Tx[ds] = L @ Tx[ss] ----------------
// 16 threads per dst node, each owns one float4. Packed 8B edge records,
// 4-edge unroll. Row bounds from mutated g_off (row d = [g_off[d-1], g_off[d])).
__global__ void spmm_csr_kernel(int ss, int ds, int n) {
    int idx = blockIdx.x * blockDim.x + threadIdx.x;
    int d = idx >> 4;
    int q = idx & 15;
    if (d >= n) return;
    int r0 = d ? __ldg(&g_off[d - 1]) : 0;
    int r1 = __ldg(&g_off[d]);
    float ax = 0.f, ay = 0.f, az = 0.f, aw = 0.f;
    float bx = 0.f, by = 0.f, bz = 0.f, bw = 0.f;
    const float4* __restrict__ src_base = (const float4*)g_tx[ss];
    const int2*  __restrict__ edges = g_edge;
    int e = r0;
    for (; e + 3 < r1; e += 4) {
        int2 r_0 = __ldg(&edges[e]);
        int2 r_1 = __ldg(&edges[e + 1]);
        int2 r_2 = __ldg(&edges[e + 2]);
        int2 r_3 = __ldg(&edges[e + 3]);
        float4 a0 = __ldg(&src_base[(size_t)r_0.x * 16 + q]);
        float4 a1 = __ldg(&src_base[(size_t)r_1.x * 16 + q]);
        float4 a2 = __ldg(&src_base[(size_t)r_2.x * 16 + q]);
        float4 a3 = __ldg(&src_base[(size_t)r_3.x * 16 + q]);
        float v0 = __int_as_float(r_0.y);
        float v1 = __int_as_float(r_1.y);
        float v2 = __int_as_float(r_2.y);
        float v3 = __int_as_float(r_3.y);
        ax += v0 * a0.x; ay += v0 * a0.y; az += v0 * a0.z; aw += v0 * a0.w;
        bx += v1 * a1.x; by += v1 * a1.y; bz += v1 * a1.z; bw += v1 * a1.w;
        ax += v2 * a2.x; ay += v2 * a2.y; az += v2 * a2.z; aw += v2 * a2.w;
        bx += v3 * a3.x; by += v3 * a3.y; bz += v3 * a3.z; bw += v3 * a3.w;
    }
    for (; e < r1; e++) {
        int2 r_0 = __ldg(&edges[e]);
        float v0 = __int_as_float(r_0.y);
        float4 a = __ldg(&src_base[(size_t)r_0.x * 16 + q]);
        ax += v0 * a.x; ay += v0 * a.y; az += v0 * a.z; aw += v0 * a.w;
    }
    float4 r; r.x = ax + bx; r.y = ay + by; r.z = az + bz; r.w = aw + bw;
    ((float4*)(g_tx[ds]))[(size_t)d * 16 + q] = r;
}

// ---------------- fused epilogue (R3 layout, measured best) ----------------
#define PW 68      // padded row stride for 64-wide weights
__global__ void epilogue_kernel(const float* __restrict__ thetas,
                                const float* __restrict__ Wb, const float* __restrict__ bWb,
                                const float* __restrict__ Wx, const float* __restrict__ bWx,
                                const float* __restrict__ vc,
                                const float* __restrict__ W1, const float* __restrict__ b1,
                                const float* __restrict__ W2, const float* __restrict__ b2,
                                const float* __restrict__ W3, const float* __restrict__ b3,
                                float* __restrict__ out, int n) {
    extern __shared__ float sm[];
    float* sWb  = sm;                 // 64*68
    float* sWx  = sWb + 64 * PW;      // 64*68
    float* sW1  = sWx + 64 * PW;      // 64*68
    float* sW2  = sW1 + 64 * PW;      // 32*68
    float* sW3  = sW2 + 32 * PW;      // 64
    float* svc  = sW3 + 64;           // 64
    float* sbWb = svc + 64;           // 64
    float* sbWx = sbWb + 64;          // 64
    float* sb1  = sbWx + 64;          // 64
    float* sb2  = sb1 + 64;           // 32
    float* sb3  = sb2 + 32;           // 2 (+2 pad)
    float* sp0  = sb3 + 4;            // 4*68
    float* sp1  = sp0 + 4 * PW;
    float* shh  = sp1 + 4 * PW;
    float* sres = shh + 4 * PW;
    float* sy1  = sres + 4 * PW;
    float* sy2  = sy1 + 4 * PW;       // 4*32
    float* sred = sy2 + 4 * 32;       // 4*4  [node][warp][filter]

    int tid = threadIdx.x;
    for (int idx = tid; idx < 4096; idx += 256) {
        int i = idx >> 6, c = idx & 63;
        sWb[c * PW + i] = Wb[idx];
        sWx[c * PW + i] = Wx[idx];
        sW1[c * PW + i] = W1[idx];
    }
    for (int idx = tid; idx < 2048; idx += 256) {
        int i = idx >> 5, c = idx & 31;
        sW2[c * PW + i] = W2[idx];
    }
    if (tid < 64) {
        sW3[tid]  = W3[tid];
        svc[tid]  = vc[tid];
        sbWb[tid] = bWb[tid];
        sbWx[tid] = bWx[tid];
        sb1[tid]  = b1[tid];
    }
    if (tid < 32) sb2[tid] = b2[tid];
    if (tid < 2)  sb3[tid] = b3[tid];

    // fold thetas with Bernstein coefficients
    float th0 = __ldg(&thetas[0]), th1 = __ldg(&thetas[1]), th2 = __ldg(&thetas[2]), th3 = __ldg(&thetas[3]);
    float tg0 = __ldg(&thetas[4]), tg1 = __ldg(&thetas[5]), tg2 = __ldg(&thetas[6]), tg3 = __ldg(&thetas[7]);
    float c00 = th0;
    float c01 = -3.f * th0 + 3.f * th1;
    float c02 =  3.f * th0 - 6.f * th1 + 3.f * th2;
    float c03 = -1.f * th0 + 3.f * th1 - 3.f * th2 + th3;
    float c10 = tg0;
    float c11 = -3.f * tg0 + 3.f * tg1;
    float c12 =  3.f * tg0 - 6.f * tg1 + 3.f * tg2;
    float c13 = -1.f * tg0 + 3.f * tg1 - 3.f * tg2 + tg3;
    __syncthreads();

    int node = tid >> 6;
    int c = tid & 63;
    int whalf = (tid >> 5) & 1;

    for (int base = blockIdx.x * 4; base < n; base += gridDim.x * 4) {
        int nid = base + node;
        bool ok = nid < n;
        float t0 = 0.f, t1v = 0.f, t2v = 0.f, t3v = 0.f;
        if (ok) {
            size_t o = (size_t)nid * 64 + c;
            t0  = g_tx[0][o];
            t1v = g_tx[1][o];
            t2v = g_tx[2][o];
            t3v = g_tx[3][o];
        }
        float p0 = c00 * t0 + c01 * t1v + c02 * t2v + c03 * t3v;
        float p1 = c10 * t0 + c11 * t1v + c12 * t2v + c13 * t3v;
        sp0[node * PW + c] = p0;
        sp1[node * PW + c] = p1;
        shh[node * PW + c] = t0;
        __syncthreads();

        float pp0 = sbWb[c], pp1 = sbWb[c], xp = sbWx[c];
        const float4* wb = (const float4*)&sWb[c * PW];
        const float4* wx = (const float4*)&sWx[c * PW];
        const float4* v0 = (const float4*)&sp0[node * PW];
        const float4* v1 = (const float4*)&sp1[node * PW];
        const float4* vh = (const float4*)&shh[node * PW];
#pragma unroll
        for (int i = 0; i < 16; i++) {
            float4 a = wb[i], b = wx[i], u = v0[i], w = v1[i], hh = vh[i];
            pp0 += a.x * u.x + a.y * u.y + a.z * u.z + a.w * u.w;
            pp1 += a.x * w.x + a.y * w.y + a.z * w.z + a.w * w.w;
            xp  += b.x * hh.x + b.y * hh.y + b.z * hh.z + b.w * hh.w;
        }
        float vcc = svc[c];
        float term0 = tanhf(pp0 + xp) * vcc;
        float term1 = tanhf(pp1 + xp) * vcc;
#pragma unroll
        for (int o = 16; o > 0; o >>= 1) {
            term0 += __shfl_xor_sync(0xffffffffu, term0, o);
            term1 += __shfl_xor_sync(0xffffffffu, term1, o);
        }
        if ((tid & 31) == 0) {
            sred[node * 4 + whalf * 2 + 0] = term0;
            sred[node * 4 + whalf * 2 + 1] = term1;
        }
        __syncthreads();
        float s0 = sred[node * 4 + 0] + sred[node * 4 + 2];
        float s1 = sred[node * 4 + 1] + sred[node * 4 + 3];
        float att0 = 1.f / (1.f + expf(s1 - s0));
        float att1 = 1.f - att0;
        float res = att0 * p0 + att1 * p1;
        sres[node * PW + c] = res;
        __syncthreads();

        float y = sb1[c];
        const float4* w1 = (const float4*)&sW1[c * PW];
        const float4* vr = (const float4*)&sres[node * PW];
#pragma unroll
        for (int i = 0; i < 16; i++) {
            float4 a = w1[i], r4 = vr[i];
            y += a.x * r4.x + a.y * r4.y + a.z * r4.z + a.w * r4.w;
        }
        sy1[node * PW + c] = fmaxf(y, 0.f);
        __syncthreads();

        if (c < 32) {
            float z = sb2[c];
            const float4* w2 = (const float4*)&sW2[c * PW];
            const float4* vy = (const float4*)&sy1[node * PW];
#pragma unroll
            for (int i = 0; i < 16; i++) {
                float4 a = w2[i], r4 = vy[i];
                z += a.x * r4.x + a.y * r4.y + a.z * r4.z + a.w * r4.w;
            }
            sy2[node * 32 + c] = fmaxf(z, 0.f);
        }
        __syncthreads();

        if (ok && c < 2) {
            float o = sb3[c];
#pragma unroll
            for (int i = 0; i < 32; i++) o += sy2[node * 32 + i] * sW3[i * 2 + c];
            out[(size_t)nid * 2 + c] = o;
        }
        __syncthreads();
    }
}

// ---------------- host launcher ----------------
extern "C" void kernel_launch(void* const* d_in, const int* in_sizes, int n_in,
                              void* d_out, int out_size) {
    const float* x     = (const float*)d_in[0];
    const void*  esrc  = d_in[1];
    const void*  edst  = d_in[2];
    const float* evals = (const float*)d_in[3];
    const float* Win   = (const float*)d_in[4];
    const float* bin   = (const float*)d_in[5];
    const float* thetas= (const float*)d_in[6];
    const float* Wb    = (const float*)d_in[7];
    const float* bWb   = (const float*)d_in[8];
    const float* Wx    = (const float*)d_in[9];
    const float* bWx   = (const float*)d_in[10];
    const float* vc    = (const float*)d_in[11];
    const float* W1    = (const float*)d_in[12];
    const float* b1    = (const float*)d_in[13];
    const float* W2    = (const float*)d_in[14];
    const float* b2    = (const float*)d_in[15];
    const float* W3    = (const float*)d_in[16];
    const float* b3    = (const float*)d_in[17];
    float* out = (float*)d_out;

    int n = in_sizes[0] / C_IN;     // 100000
    int E = in_sizes[3];            // 1600000
    int eb = (E + 255) / 256;
    int nt = (n + 1023) / 1024;     // 98 lookback tiles

    // Launch order chosen so the ncu capture window (4th kernel) = gemm_in.
    detect_kernel<<<1, 128>>>(esrc);                       // 0
    hist_kernel<<<eb, 256>>>(edst, E);                     // 1
    scan_kernel<<<nt, 1024>>>(n);                          // 2
    gemm_in_kernel<<<1480, 256>>>(x, Win, bin, n);         // 3  <- profiled
    scatter_kernel<<<eb, 256>>>(esrc, edst, evals, E);     // 4

    int sb = (n * 16 + 255) / 256;
    spmm_csr_kernel<<<sb, 256>>>(0, 1, n);                 // 5
    spmm_csr_kernel<<<sb, 256>>>(1, 2, n);                 // 6
    spmm_csr_kernel<<<sb, 256>>>(2, 3, n);                 // 7

    size_t smem = (size_t)(3 * 64 * PW + 32 * PW + 64 * 5 + 32 + 4 + 5 * 4 * PW + 4 * 32 + 16) * sizeof(float);
    cudaFuncSetAttribute(epilogue_kernel, cudaFuncAttributeMaxDynamicSharedMemorySize, (int)smem);
    epilogue_kernel<<<444, 256, smem>>>(thetas, Wb, bWb, Wx, bWx, vc,
                                        W1, b1, W2, b2, W3, b3, out, n);  // 8
    (void)n_in; (void)out_size;
}